// round 1
// baseline (speedup 1.0000x reference)
#include <cuda_runtime.h>
#include <cuda_bf16.h>
#include <cstdint>

#define D_MODEL 1024
#define NUM_T   2048
#define BATCH   32

#define PE_ELEMS (NUM_T * D_MODEL)            // 2,097,152
#define PE_VEC4  (PE_ELEMS / 4)               // 524,288  (power of two)
#define TOTAL_ELEMS ((long long)BATCH * PE_ELEMS)   // 67,108,864
#define TOTAL_VEC4  (TOTAL_ELEMS / 4)         // 16,777,216

// 8 MB scratch for the positional-encoding table (allowed: __device__ global)
__device__ float g_pe[PE_ELEMS];

// Kernel 1: build PE table. pe[t,i] = sin/cos( t / 10000^(2i/D) )
__global__ void pe_build_kernel() {
    int idx = blockIdx.x * blockDim.x + threadIdx.x;
    if (idx >= PE_ELEMS) return;
    int t = idx >> 10;          // idx / D_MODEL
    int i = idx & (D_MODEL - 1);
    // match reference fp32 math: pos / powf(10000, 2*i/D)
    float denom = powf(10000.0f, (2.0f * (float)i) / (float)D_MODEL);
    float angle = (float)t / denom;
    g_pe[idx] = (i & 1) ? cosf(angle) : sinf(angle);
}

// Kernel 2: out = x + pe (broadcast over batch), float4 vectorized
__global__ void __launch_bounds__(256) add_pe_kernel(const float4* __restrict__ x,
                                                     float4* __restrict__ out) {
    unsigned idx = blockIdx.x * blockDim.x + threadIdx.x;
    if (idx >= (unsigned)TOTAL_VEC4) return;
    const float4* pe4 = reinterpret_cast<const float4*>(g_pe);
    float4 xv = x[idx];
    float4 pv = pe4[idx & (PE_VEC4 - 1u)];
    float4 o;
    o.x = xv.x + pv.x;
    o.y = xv.y + pv.y;
    o.z = xv.z + pv.z;
    o.w = xv.w + pv.w;
    out[idx] = o;
}

extern "C" void kernel_launch(void* const* d_in, const int* in_sizes, int n_in,
                              void* d_out, int out_size) {
    const float4* x = (const float4*)d_in[0];
    float4* out = (float4*)d_out;

    // Build PE table (tiny: 2M elems)
    pe_build_kernel<<<(PE_ELEMS + 255) / 256, 256>>>();

    // Broadcast add (64M elems as 16M float4)
    add_pe_kernel<<<(int)((TOTAL_VEC4 + 255) / 256), 256>>>(x, out);
}

// round 2
// speedup vs baseline: 1.0876x; 1.0876x over previous
#include <cuda_runtime.h>
#include <cuda_bf16.h>
#include <cstdint>

#define D_MODEL 1024
#define NUM_T   2048
#define BATCH   32

#define PE_ELEMS (NUM_T * D_MODEL)            // 2,097,152
#define PE_VEC4  (PE_ELEMS / 4)               // 524,288  (power of two)
#define TOTAL_ELEMS ((long long)BATCH * PE_ELEMS)   // 67,108,864
#define TOTAL_VEC4  (TOTAL_ELEMS / 4)         // 16,777,216

#define T_CHUNK 64                            // rows per recurrence chunk

// 8 MB scratch for the positional-encoding table (allowed: __device__ global)
__device__ float g_pe[PE_ELEMS];

// Kernel 1: build PE table via angle-addition recurrence.
// One warp = 32 adjacent columns (i) x one 64-row t-chunk.
// Per thread: 2 precise sincosf, then 64 steps of 4 FMAs.
// Stores per step are 32 consecutive floats -> fully coalesced 128B.
__global__ void __launch_bounds__(256) pe_build_kernel() {
    const int gwarp = (blockIdx.x * blockDim.x + threadIdx.x) >> 5;
    const int lane  = threadIdx.x & 31;

    const int col_group = gwarp & 31;          // 32 column-groups
    const int t_chunk   = gwarp >> 5;          // 32 t-chunks
    const int i  = col_group * 32 + lane;      // column 0..1023
    const int t0 = t_chunk * T_CHUNK;

    // match reference fp32 math: denom = powf(10000, 2*i/D); angle = t / denom
    const float denom = powf(10000.0f, (2.0f * (float)i) / (float)D_MODEL);
    const float inv   = 1.0f / denom;          // per-step angle increment

    float s, c, sd, cd;
    sincosf((float)t0 * inv, &s, &c);          // exact start of chunk
    sincosf(inv, &sd, &cd);                    // rotation step

    const bool use_sin = ((i & 1) == 0);
    float* row = g_pe + t0 * D_MODEL + i;

    #pragma unroll 8
    for (int k = 0; k < T_CHUNK; k++) {
        *row = use_sin ? s : c;
        row += D_MODEL;
        float s2 = fmaf(s, cd,  c * sd);
        float c2 = fmaf(c, cd, -s * sd);
        s = s2; c = c2;
    }
}

// Kernel 2: out = x + pe (broadcast over batch).
// 4 grid-strided float4 per thread for MLP; streaming hints keep PE in L2.
#define ITEMS 4
__global__ void __launch_bounds__(256) add_pe_kernel(const float4* __restrict__ x,
                                                     float4* __restrict__ out) {
    const unsigned stride = gridDim.x * blockDim.x;          // = TOTAL_VEC4 / ITEMS
    const unsigned base = blockIdx.x * blockDim.x + threadIdx.x;
    const float4* pe4 = reinterpret_cast<const float4*>(g_pe);

    unsigned id[ITEMS];
    float4 xv[ITEMS], pv[ITEMS];
    #pragma unroll
    for (int k = 0; k < ITEMS; k++) {
        id[k] = base + (unsigned)k * stride;
        xv[k] = __ldcs(&x[id[k]]);                           // streaming read
    }
    #pragma unroll
    for (int k = 0; k < ITEMS; k++) {
        pv[k] = __ldg(&pe4[id[k] & (PE_VEC4 - 1u)]);         // L2-resident PE
    }
    #pragma unroll
    for (int k = 0; k < ITEMS; k++) {
        float4 o;
        o.x = xv[k].x + pv[k].x;
        o.y = xv[k].y + pv[k].y;
        o.z = xv[k].z + pv[k].z;
        o.w = xv[k].w + pv[k].w;
        __stcs(&out[id[k]], o);                              // streaming write
    }
}

extern "C" void kernel_launch(void* const* d_in, const int* in_sizes, int n_in,
                              void* d_out, int out_size) {
    const float4* x = (const float4*)d_in[0];
    float4* out = (float4*)d_out;

    // PE build: 1024 warps = 32768 threads
    pe_build_kernel<<<(32 * 32 * 32) / 256, 256>>>();

    // Broadcast add: exact cover, no tail (16M vec4 / (256*4) = 16384 blocks)
    add_pe_kernel<<<(int)(TOTAL_VEC4 / (256 * ITEMS)), 256>>>(x, out);
}